// round 11
// baseline (speedup 1.0000x reference)
#include <cuda_runtime.h>
#include <cstdint>

#define BH 32
#define L 2048
#define D 64
#define WIN 2
#define QBLK 528
#define SMEMB (1024 + 64 * QBLK)   // rows_s + Q A-frag trampoline = 34816B

__device__ __forceinline__ uint32_t rna(float x) {
    uint32_t r; asm("cvt.rna.tf32.f32 %0, %1;" : "=r"(r) : "f"(x)); return r;
}
__device__ __forceinline__ void mma8(float* d, uint32_t a0, uint32_t a1, uint32_t a2, uint32_t a3,
                                     uint32_t b0, uint32_t b1) {
    asm volatile("mma.sync.aligned.m16n8k8.row.col.f32.tf32.tf32.f32 "
        "{%0,%1,%2,%3}, {%4,%5,%6,%7}, {%8,%9}, {%0,%1,%2,%3};"
        : "+f"(d[0]), "+f"(d[1]), "+f"(d[2]), "+f"(d[3])
        : "r"(a0), "r"(a1), "r"(a2), "r"(a3), "r"(b0), "r"(b1));
}

__device__ int g_perm[BH][L];
__device__ int g_cnt[BH][2];
__device__ float g_out_scr[(size_t)BH * L * D];
__device__ float g_attn_scr[(size_t)BH * L * L];
// fragment-order tf32 copies of K and V (16MB each, L2-resident)
// ktr: uint2 index ((bh*256+ntG)*8+ks)*32 + lane  ->  (K[ntG*8+g][8ks+tg], K[ntG*8+g][8ks+tg+4])
// vtr: uint2 index ((bh*8+ntd)*256+ntG)*32 + lane ->  (V[ntG*8+tg][8ntd+g], V[ntG*8+tg+4][8ntd+g])
__device__ float g_ktr[(size_t)BH * L * D];
__device__ float g_vtr[(size_t)BH * L * D];

// ---------------------------------------------------------------------------
__global__ void gate_init() {
    int t = threadIdx.x;
    if (t < BH) { g_cnt[t][0] = 0; g_cnt[t][1] = 0; }
}

__global__ void __launch_bounds__(256)
gate_kernel(const float* __restrict__ q, const float* __restrict__ gw, const float* __restrict__ gb) {
    __shared__ float4 w_s[16];
    const int bh = blockIdx.x >> 3, seg = blockIdx.x & 7;
    const int t = threadIdx.x;
    if (t < 16) w_s[t] = ((const float4*)gw)[t];
    __syncthreads();
    const int r = seg * 256 + t;
    const float4* qr = (const float4*)(q + ((size_t)bh * L + r) * D);
    float s = gb[0];
#pragma unroll
    for (int c = 0; c < 16; c++) {
        float4 a = qr[c], w = w_s[c];
        s += a.x * w.x + a.y * w.y + a.z * w.z + a.w * w.w;
    }
    if (s > 0.f) g_perm[bh][atomicAdd(&g_cnt[bh][0], 1)] = r;
    else         g_perm[bh][L - 1 - atomicAdd(&g_cnt[bh][1], 1)] = r;
}

// ---------------------------------------------------------------------------
// K/V -> fragment-order tf32 global arrays.
// ---------------------------------------------------------------------------
__global__ void __launch_bounds__(256)
trans_kv(const float* __restrict__ k, const float* __restrict__ v) {
    const int bh = blockIdx.y, bx = blockIdx.x, t = threadIdx.x;
    if (bx < 64) {      // K: unit = (ntG, ks, g): 2 LDG.128 -> 2 STG.128
        int u = bx * 256 + t;
        int ntG = u >> 6, ks = (u >> 3) & 7, g = u & 7;
        const float4* kr = (const float4*)(k + ((size_t)bh * L + ntG * 8 + g) * D);
        float4 a = kr[2 * ks], b = kr[2 * ks + 1];
        char* bp = (char*)g_ktr + ((((size_t)bh * 256 + ntG) * 8 + ks) << 8) + g * 32;
        *(uint4*)bp        = make_uint4(rna(a.x), rna(b.x), rna(a.y), rna(b.y));
        *(uint4*)(bp + 16) = make_uint4(rna(a.z), rna(b.z), rna(a.w), rna(b.w));
    } else {            // V: unit = (ntG, c4, kk): 1 LDG.128 -> 4 STG.32
        int u = (bx - 64) * 256 + t;
        int ntG = u >> 7, c4 = (u >> 3) & 15, kk = u & 7;
        float4 vv = ((const float4*)(v + ((size_t)bh * L + ntG * 8 + kk) * D))[c4];
        float f[4] = {vv.x, vv.y, vv.z, vv.w};
        int tg = kk & 3, el = kk >> 2;
#pragma unroll
        for (int e = 0; e < 4; e++) {
            int d = 4 * c4 + e;
            char* p = (char*)g_vtr + ((((size_t)bh * 8 + (d >> 3)) * 256 + ntG) << 8)
                      + (d & 7) * 32 + tg * 8 + el * 4;
            *(uint32_t*)p = rna(f[e]);
        }
    }
}

// ---------------------------------------------------------------------------
// Fat kernel: bx<16 -> gated attention (128 rows), bx in [16,48) -> windowed (64 rows).
// ---------------------------------------------------------------------------
__global__ void __launch_bounds__(256, 2)
attn_fat(const float* __restrict__ q, const float* __restrict__ k,
         const float* __restrict__ v, float* attnp, float* outp) {
    extern __shared__ __align__(16) char sm[];
    float* attn = attnp ? attnp : g_attn_scr;
    float* out  = outp  ? outp  : g_out_scr;
    const int bh = blockIdx.y, bx = blockIdx.x;
    const int t = threadIdx.x, w = t >> 5, lane = t & 31;
    const int g = lane >> 2, tg = lane & 3;

    // ================= windowed rows =================
    if (bx >= 16) {
        const int nw = L - g_cnt[bh][0];
        for (int rr = 0; rr < 8; rr++) {
            const int widx = (bx - 16) * 64 + w * 8 + rr;
            if (widx >= nw) break;
            const int i = g_perm[bh][L - 1 - widx];
            const int j0 = max(0, i - WIN), j1 = min(L - 1, i + WIN);
            const int n = j1 - j0 + 1;
            const float* qr = q + ((size_t)bh * L + i) * D;
            float q0 = qr[lane], q1 = qr[lane + 32];
            float p[5], mx = -3.0e38f;
#pragma unroll
            for (int jj = 0; jj < 5; jj++) {
                float sc = -3.0e38f;
                if (jj < n) {
                    const float* kr = k + ((size_t)bh * L + j0 + jj) * D;
                    float d = q0 * kr[lane] + q1 * kr[lane + 32];
#pragma unroll
                    for (int o = 16; o > 0; o >>= 1) d += __shfl_xor_sync(0xffffffffu, d, o);
                    sc = d * 0.125f;
                }
                p[jj] = sc; mx = fmaxf(mx, sc);
            }
            float sum = 0.f;
#pragma unroll
            for (int jj = 0; jj < 5; jj++) { p[jj] = (jj < n) ? __expf(p[jj] - mx) : 0.f; sum += p[jj]; }
            float inv = 1.0f / sum;
#pragma unroll
            for (int jj = 0; jj < 5; jj++) p[jj] *= inv;

            float4* arow4 = (float4*)(attn + ((size_t)bh * L + i) * (size_t)L);
            const int s_lo = j0 >> 2, s_hi = j1 >> 2;
#pragma unroll
            for (int it = 0; it < 16; it++) {
                int s4 = lane + it * 32;
                if (s4 < s_lo || s4 > s_hi) arow4[s4] = make_float4(0.f, 0.f, 0.f, 0.f);
            }
            if (lane <= s_hi - s_lo) {
                int s4 = s_lo + lane;
                float vv[4];
#pragma unroll
                for (int e = 0; e < 4; e++) {
                    int idx = s4 * 4 + e;
                    vv[e] = (idx >= j0 && idx <= j1) ? p[idx - j0] : 0.f;
                }
                arow4[s4] = make_float4(vv[0], vv[1], vv[2], vv[3]);
            }
            float o0 = 0.f, o1 = 0.f;
#pragma unroll
            for (int jj = 0; jj < 5; jj++) {
                if (jj < n) {
                    const float* vr = v + ((size_t)bh * L + j0 + jj) * D;
                    o0 += p[jj] * vr[lane];
                    o1 += p[jj] * vr[lane + 32];
                }
            }
            float* orow = out + ((size_t)bh * L + i) * D;
            orow[lane] = o0; orow[lane + 32] = o1;
        }
        return;
    }

    // ================= gated rows =================
    const int ng = g_cnt[bh][0];
    const int base = bx * 128;
    if (base >= ng) return;
    int* rows_s = (int*)sm;
    if (t < 128) { int s = base + t; rows_s[t] = g_perm[bh][s < ng ? s : ng - 1]; }
    __syncthreads();

    // Q A-frags via smem trampoline (x 1/8, tf32)
#pragma unroll
    for (int it = 0; it < 2; it++) {
        int u = t + it * 256;
        int ks = u & 7, rp = (u >> 3) & 7, wt = u >> 6;
        int r0 = wt * 16 + rp, r1 = r0 + 8;
        const float4* q0 = (const float4*)(q + ((size_t)bh * L + rows_s[r0]) * D);
        const float4* q1 = (const float4*)(q + ((size_t)bh * L + rows_s[r1]) * D);
        float4 a0 = q0[2 * ks], a1 = q0[2 * ks + 1];
        float4 b0 = q1[2 * ks], b1 = q1[2 * ks + 1];
        char* bp = sm + 1024 + (wt * 8 + ks) * QBLK + rp * 64;
        *(uint4*)bp        = make_uint4(rna(a0.x * .125f), rna(b0.x * .125f), rna(a1.x * .125f), rna(b1.x * .125f));
        *(uint4*)(bp + 16) = make_uint4(rna(a0.y * .125f), rna(b0.y * .125f), rna(a1.y * .125f), rna(b1.y * .125f));
        *(uint4*)(bp + 32) = make_uint4(rna(a0.z * .125f), rna(b0.z * .125f), rna(a1.z * .125f), rna(b1.z * .125f));
        *(uint4*)(bp + 48) = make_uint4(rna(a0.w * .125f), rna(b0.w * .125f), rna(a1.w * .125f), rna(b1.w * .125f));
    }
    __syncthreads();
    uint4 qh4[8];
#pragma unroll
    for (int ks = 0; ks < 8; ks++)
        qh4[ks] = *(const uint4*)(sm + 1024 + (w * 8 + ks) * QBLK + lane * 16);

    const uint2* kfr = (const uint2*)g_ktr + (size_t)bh * 256 * 8 * 32 + lane;
    const uint2* vfr = (const uint2*)g_vtr + (size_t)bh * 8 * 256 * 32 + lane;

    // ---------------- Pass A: row sums ----------------
    float sum0 = 0.f, sum8 = 0.f;
#pragma unroll 2
    for (int n = 0; n < 256; n++) {
        float dd[4] = {0.f, 0.f, 0.f, 0.f};
        const uint2* kb = kfr + n * 256;
#pragma unroll
        for (int ks = 0; ks < 8; ks++) {
            uint2 kk = kb[ks * 32];
            mma8(dd, qh4[ks].x, qh4[ks].y, qh4[ks].z, qh4[ks].w, kk.x, kk.y);
        }
        sum0 += __expf(dd[0]) + __expf(dd[1]);
        sum8 += __expf(dd[2]) + __expf(dd[3]);
    }
    sum0 += __shfl_xor_sync(0xffffffffu, sum0, 1);
    sum0 += __shfl_xor_sync(0xffffffffu, sum0, 2);
    sum8 += __shfl_xor_sync(0xffffffffu, sum8, 1);
    sum8 += __shfl_xor_sync(0xffffffffu, sum8, 2);
    const float inv0 = 1.f / sum0, inv8 = 1.f / sum8;

    // ---------------- Pass B: probs + AV ----------------
    const int rb0 = w * 16 + g;
    const bool vr0 = base + rb0 < ng, vr8 = base + rb0 + 8 < ng;
    float* arow0 = attn + ((size_t)bh * L + rows_s[rb0]) * (size_t)L;
    float* arow8 = attn + ((size_t)bh * L + rows_s[rb0 + 8]) * (size_t)L;
    float avD[8][4];
#pragma unroll
    for (int i = 0; i < 8; i++) { avD[i][0] = avD[i][1] = avD[i][2] = avD[i][3] = 0.f; }

    const int src0 = (lane & 28) | (tg >> 1);
    const int src2 = src0 + 2;
    const bool odd = tg & 1;

    for (int n = 0; n < 256; n++) {
        float dd[4] = {0.f, 0.f, 0.f, 0.f};
        const uint2* kb = kfr + n * 256;
#pragma unroll
        for (int ks = 0; ks < 8; ks++) {
            uint2 kk = kb[ks * 32];
            mma8(dd, qh4[ks].x, qh4[ks].y, qh4[ks].z, qh4[ks].w, kk.x, kk.y);
        }
        float p0 = __expf(dd[0]) * inv0, p1 = __expf(dd[1]) * inv0;
        float p2 = __expf(dd[2]) * inv8, p3 = __expf(dd[3]) * inv8;
        int co = n * 8 + 2 * tg;
        if (vr0) *(float2*)(arow0 + co) = make_float2(p0, p1);
        if (vr8) *(float2*)(arow8 + co) = make_float2(p2, p3);
        uint32_t h0 = rna(p0), h1 = rna(p1), h2 = rna(p2), h3 = rna(p3);
        uint32_t x00 = __shfl_sync(0xffffffffu, h0, src0), x01 = __shfl_sync(0xffffffffu, h1, src0);
        uint32_t x20 = __shfl_sync(0xffffffffu, h2, src0), x21 = __shfl_sync(0xffffffffu, h3, src0);
        uint32_t y00 = __shfl_sync(0xffffffffu, h0, src2), y01 = __shfl_sync(0xffffffffu, h1, src2);
        uint32_t y20 = __shfl_sync(0xffffffffu, h2, src2), y21 = __shfl_sync(0xffffffffu, h3, src2);
        uint32_t a0 = odd ? x01 : x00, a1 = odd ? x21 : x20;
        uint32_t a2 = odd ? y01 : y00, a3 = odd ? y21 : y20;
#pragma unroll
        for (int ntd = 0; ntd < 8; ntd++) {
            uint2 vv = vfr[(ntd * 256 + n) * 32];
            mma8(avD[ntd], a0, a1, a2, a3, vv.x, vv.y);
        }
    }

    float* orow0 = out + ((size_t)bh * L + rows_s[rb0]) * D;
    float* orow8 = out + ((size_t)bh * L + rows_s[rb0 + 8]) * D;
#pragma unroll
    for (int ntd = 0; ntd < 8; ntd++) {
        int dc = ntd * 8 + 2 * tg;
        if (vr0) *(float2*)(orow0 + dc) = make_float2(avD[ntd][0], avD[ntd][1]);
        if (vr8) *(float2*)(orow8 + dc) = make_float2(avD[ntd][2], avD[ntd][3]);
    }
}

// ---------------------------------------------------------------------------
extern "C" void kernel_launch(void* const* d_in, const int* in_sizes, int n_in,
                              void* d_out, int out_size) {
    const float* q  = (const float*)d_in[0];
    const float* k  = (const float*)d_in[1];
    const float* v  = (const float*)d_in[2];
    const float* gw = (const float*)d_in[3];
    const float* gb = (const float*)d_in[4];

    const long long OUTE = (long long)BH * L * D;
    const long long ATTE = (long long)BH * L * L;
    float* outp = nullptr; float* attnp = nullptr;
    if ((long long)out_size == OUTE + ATTE) { outp = (float*)d_out; attnp = (float*)d_out + OUTE; }
    else if ((long long)out_size == ATTE)   { attnp = (float*)d_out; }
    else                                    { outp = (float*)d_out; }

    cudaFuncSetAttribute(attn_fat, cudaFuncAttributeMaxDynamicSharedMemorySize, SMEMB);
    gate_init<<<1, 64>>>();
    gate_kernel<<<BH * 8, 256>>>(q, gw, gb);
    trans_kv<<<dim3(192, BH), 256>>>(k, v);
    attn_fat<<<dim3(48, BH), 256, SMEMB>>>(q, k, v, attnp, outp);
}

// round 12
// speedup vs baseline: 1.3177x; 1.3177x over previous
#include <cuda_runtime.h>
#include <cstdint>

#define BH 32
#define L 2048
#define D 64
#define TK 128
#define NTILE (L / TK)
#define WIN 2

#define KOFF 1024
#define KBLK 272                 // K/V (nt*8+ks) block stride: 256B data + 16B pad
#define QBLK 528                 // Q A-frag block stride: 512B data + 16B pad
#define VOFF (KOFF + 128 * KBLK) // 35840
#define VNTD 4368                // ntd stride: 16*272 + 16
#define SMEMB (VOFF + 8 * VNTD)  // 70784

__device__ __forceinline__ uint32_t rna(float x) {
    uint32_t r; asm("cvt.rna.tf32.f32 %0, %1;" : "=r"(r) : "f"(x)); return r;
}
__device__ __forceinline__ void mma8(float* d, uint32_t a0, uint32_t a1, uint32_t a2, uint32_t a3,
                                     uint32_t b0, uint32_t b1) {
    asm volatile("mma.sync.aligned.m16n8k8.row.col.f32.tf32.tf32.f32 "
        "{%0,%1,%2,%3}, {%4,%5,%6,%7}, {%8,%9}, {%0,%1,%2,%3};"
        : "+f"(d[0]), "+f"(d[1]), "+f"(d[2]), "+f"(d[3])
        : "r"(a0), "r"(a1), "r"(a2), "r"(a3), "r"(b0), "r"(b1));
}

__device__ int g_perm[BH][L];
__device__ int g_cnt[BH][2];
__device__ float g_out_scr[(size_t)BH * L * D];
__device__ float g_attn_scr[(size_t)BH * L * L];

// ---------------------------------------------------------------------------
__global__ void gate_init() {
    int t = threadIdx.x;
    if (t < BH) { g_cnt[t][0] = 0; g_cnt[t][1] = 0; }
}

__global__ void __launch_bounds__(256)
gate_kernel(const float* __restrict__ q, const float* __restrict__ gw, const float* __restrict__ gb) {
    __shared__ float4 w_s[16];
    const int bh = blockIdx.x >> 3, seg = blockIdx.x & 7;
    const int t = threadIdx.x;
    if (t < 16) w_s[t] = ((const float4*)gw)[t];
    __syncthreads();
    const int r = seg * 256 + t;
    const float4* qr = (const float4*)(q + ((size_t)bh * L + r) * D);
    float s = gb[0];
#pragma unroll
    for (int c = 0; c < 16; c++) {
        float4 a = qr[c], w = w_s[c];
        s += a.x * w.x + a.y * w.y + a.z * w.z + a.w * w.w;
    }
    if (s > 0.f) g_perm[bh][atomicAdd(&g_cnt[bh][0], 1)] = r;
    else         g_perm[bh][L - 1 - atomicAdd(&g_cnt[bh][1], 1)] = r;
}

// ---------------------------------------------------------------------------
// stage one K tile (128 keys x 64 dims) as tf32-hi B-fragments. 128 threads.
// ---------------------------------------------------------------------------
__device__ __forceinline__ void stage_k(const float* __restrict__ kg, char* sm, int t) {
#pragma unroll
    for (int it = 0; it < 8; it++) {
        int u = t + it * 128;
        int ks = u & 7, key = u >> 3;
        const float4* kr = (const float4*)(kg + (size_t)key * D);
        float4 a = kr[2 * ks], b = kr[2 * ks + 1];
        int nt = key >> 3, gg = key & 7;
        char* bp = sm + KOFF + (nt * 8 + ks) * KBLK + gg * 32;
        *(uint4*)bp        = make_uint4(rna(a.x), rna(b.x), rna(a.y), rna(b.y));
        *(uint4*)(bp + 16) = make_uint4(rna(a.z), rna(b.z), rna(a.w), rna(b.w));
    }
}

// ---------------------------------------------------------------------------
// Fat kernel (128 threads, 4 warps): bx<16 gated (128 rows, 32 rows/warp),
// bx in [16,48) windowed (64 rows, 16 rows/warp).
// ---------------------------------------------------------------------------
__global__ void __launch_bounds__(128, 2)
attn_fat(const float* __restrict__ q, const float* __restrict__ k,
         const float* __restrict__ v, float* attnp, float* outp) {
    extern __shared__ __align__(16) char sm[];
    float* attn = attnp ? attnp : g_attn_scr;
    float* out  = outp  ? outp  : g_out_scr;
    const int bh = blockIdx.y, bx = blockIdx.x;
    const int t = threadIdx.x, w = t >> 5, lane = t & 31;
    const int g = lane >> 2, tg = lane & 3;

    // ================= windowed rows =================
    if (bx >= 16) {
        const int nw = L - g_cnt[bh][0];
        for (int rr = 0; rr < 16; rr++) {
            const int widx = (bx - 16) * 64 + w * 16 + rr;
            if (widx >= nw) break;
            const int i = g_perm[bh][L - 1 - widx];
            const int j0 = max(0, i - WIN), j1 = min(L - 1, i + WIN);
            const int n = j1 - j0 + 1;
            const float* qr = q + ((size_t)bh * L + i) * D;
            float q0 = qr[lane], q1 = qr[lane + 32];
            float p[5], mx = -3.0e38f;
#pragma unroll
            for (int jj = 0; jj < 5; jj++) {
                float sc = -3.0e38f;
                if (jj < n) {
                    const float* kr = k + ((size_t)bh * L + j0 + jj) * D;
                    float d = q0 * kr[lane] + q1 * kr[lane + 32];
#pragma unroll
                    for (int o = 16; o > 0; o >>= 1) d += __shfl_xor_sync(0xffffffffu, d, o);
                    sc = d * 0.125f;
                }
                p[jj] = sc; mx = fmaxf(mx, sc);
            }
            float sum = 0.f;
#pragma unroll
            for (int jj = 0; jj < 5; jj++) { p[jj] = (jj < n) ? __expf(p[jj] - mx) : 0.f; sum += p[jj]; }
            float inv = 1.0f / sum;
#pragma unroll
            for (int jj = 0; jj < 5; jj++) p[jj] *= inv;

            float4* arow4 = (float4*)(attn + ((size_t)bh * L + i) * (size_t)L);
            const int s_lo = j0 >> 2, s_hi = j1 >> 2;
#pragma unroll
            for (int it = 0; it < 16; it++) {
                int s4 = lane + it * 32;
                if (s4 < s_lo || s4 > s_hi) arow4[s4] = make_float4(0.f, 0.f, 0.f, 0.f);
            }
            if (lane <= s_hi - s_lo) {
                int s4 = s_lo + lane;
                float vv[4];
#pragma unroll
                for (int e = 0; e < 4; e++) {
                    int idx = s4 * 4 + e;
                    vv[e] = (idx >= j0 && idx <= j1) ? p[idx - j0] : 0.f;
                }
                arow4[s4] = make_float4(vv[0], vv[1], vv[2], vv[3]);
            }
            float o0 = 0.f, o1 = 0.f;
#pragma unroll
            for (int jj = 0; jj < 5; jj++) {
                if (jj < n) {
                    const float* vr = v + ((size_t)bh * L + j0 + jj) * D;
                    o0 += p[jj] * vr[lane];
                    o1 += p[jj] * vr[lane + 32];
                }
            }
            float* orow = out + ((size_t)bh * L + i) * D;
            orow[lane] = o0; orow[lane + 32] = o1;
        }
        return;
    }

    // ================= gated rows =================
    const int ng = g_cnt[bh][0];
    const int base = bx * 128;
    if (base >= ng) return;
    int* rows_s = (int*)sm;
    if (t < 128) { int s = base + t; rows_s[t] = g_perm[bh][s < ng ? s : ng - 1]; }
    __syncthreads();

    // ---- stage Q A-frags (x 1/8, tf32) into K region with QBLK stride ----
#pragma unroll
    for (int it = 0; it < 4; it++) {
        int u = t + it * 128;
        int ks = u & 7, rp = (u >> 3) & 7, wt = u >> 6;
        int r0 = wt * 16 + rp, r1 = r0 + 8;
        const float4* q0 = (const float4*)(q + ((size_t)bh * L + rows_s[r0]) * D);
        const float4* q1 = (const float4*)(q + ((size_t)bh * L + rows_s[r1]) * D);
        float4 a0 = q0[2 * ks], a1 = q0[2 * ks + 1];
        float4 b0 = q1[2 * ks], b1 = q1[2 * ks + 1];
        char* bp = sm + KOFF + (wt * 8 + ks) * QBLK + rp * 64;
        *(uint4*)bp        = make_uint4(rna(a0.x * .125f), rna(b0.x * .125f), rna(a1.x * .125f), rna(b1.x * .125f));
        *(uint4*)(bp + 16) = make_uint4(rna(a0.y * .125f), rna(b0.y * .125f), rna(a1.y * .125f), rna(b1.y * .125f));
        *(uint4*)(bp + 32) = make_uint4(rna(a0.z * .125f), rna(b0.z * .125f), rna(a1.z * .125f), rna(b1.z * .125f));
        *(uint4*)(bp + 48) = make_uint4(rna(a0.w * .125f), rna(b0.w * .125f), rna(a1.w * .125f), rna(b1.w * .125f));
    }
    __syncthreads();

    // A fragments for this warp's two 16-row tiles: wt = 2w + h
    uint4 qh4[2][8];
#pragma unroll
    for (int h = 0; h < 2; h++)
#pragma unroll
        for (int ks = 0; ks < 8; ks++)
            qh4[h][ks] = *(const uint4*)(sm + KOFF + ((2 * w + h) * 8 + ks) * QBLK + lane * 16);
    __syncthreads();   // all qh4 loads done before pass A overwrites the region

    // ---------------- Pass A: row sums ----------------
    float sums[2][2] = {{0.f, 0.f}, {0.f, 0.f}};
    for (int kt = 0; kt < NTILE; kt++) {
        __syncthreads();
        stage_k(k + ((size_t)bh * L + kt * TK) * D, sm, t);
        __syncthreads();
        for (int nt = 0; nt < 16; nt++) {
            uint2 kk[8];
#pragma unroll
            for (int ks = 0; ks < 8; ks++)
                kk[ks] = *(const uint2*)(sm + KOFF + (nt * 8 + ks) * KBLK + lane * 8);
#pragma unroll
            for (int h = 0; h < 2; h++) {
                float dd[4] = {0.f, 0.f, 0.f, 0.f};
#pragma unroll
                for (int ks = 0; ks < 8; ks++)
                    mma8(dd, qh4[h][ks].x, qh4[h][ks].y, qh4[h][ks].z, qh4[h][ks].w, kk[ks].x, kk[ks].y);
                sums[h][0] += __expf(dd[0]) + __expf(dd[1]);
                sums[h][1] += __expf(dd[2]) + __expf(dd[3]);
            }
        }
    }
    float invs[2][2];
#pragma unroll
    for (int h = 0; h < 2; h++)
#pragma unroll
        for (int u = 0; u < 2; u++) {
            float s = sums[h][u];
            s += __shfl_xor_sync(0xffffffffu, s, 1);
            s += __shfl_xor_sync(0xffffffffu, s, 2);
            invs[h][u] = 1.f / s;
        }

    // ---------------- Pass B: probs + AV ----------------
    bool vr0[2], vr8[2];
    float* arow0[2];
    float* arow8[2];
#pragma unroll
    for (int h = 0; h < 2; h++) {
        int rb0 = (2 * w + h) * 16 + g;
        vr0[h] = base + rb0 < ng;
        vr8[h] = base + rb0 + 8 < ng;
        arow0[h] = attn + ((size_t)bh * L + rows_s[rb0]) * (size_t)L;
        arow8[h] = attn + ((size_t)bh * L + rows_s[rb0 + 8]) * (size_t)L;
    }
    float avD[2][8][4];
#pragma unroll
    for (int h = 0; h < 2; h++)
#pragma unroll
        for (int i = 0; i < 8; i++)
            avD[h][i][0] = avD[h][i][1] = avD[h][i][2] = avD[h][i][3] = 0.f;

    const int src0 = (lane & 28) | (tg >> 1);
    const int src2 = src0 + 2;
    const bool odd = tg & 1;

    for (int kt = 0; kt < NTILE; kt++) {
        __syncthreads();
        stage_k(k + ((size_t)bh * L + kt * TK) * D, sm, t);
        {   // stage V: unit = (key-pair, c4)
            const float* vg = v + ((size_t)bh * L + kt * TK) * D;
#pragma unroll
            for (int it = 0; it < 8; it++) {
                int u = t + it * 128;
                int c4 = u & 15, pr = u >> 4;
                int nt = pr >> 2, ttg = pr & 3;
                int key0 = nt * 8 + ttg;
                float4 v0 = ((const float4*)(vg + (size_t)key0 * D))[c4];
                float4 v1 = ((const float4*)(vg + (size_t)(key0 + 4) * D))[c4];
                int d0 = 4 * c4;
                int ntd = d0 >> 3, g0 = d0 & 7;
                char* bp = sm + VOFF + ntd * VNTD + nt * KBLK + ttg * 8;
                *(uint2*)(bp + (g0 + 0) * 32) = make_uint2(rna(v0.x), rna(v1.x));
                *(uint2*)(bp + (g0 + 1) * 32) = make_uint2(rna(v0.y), rna(v1.y));
                *(uint2*)(bp + (g0 + 2) * 32) = make_uint2(rna(v0.z), rna(v1.z));
                *(uint2*)(bp + (g0 + 3) * 32) = make_uint2(rna(v0.w), rna(v1.w));
            }
        }
        __syncthreads();

        for (int nt = 0; nt < 16; nt++) {
            uint2 kk[8];
#pragma unroll
            for (int ks = 0; ks < 8; ks++)
                kk[ks] = *(const uint2*)(sm + KOFF + (nt * 8 + ks) * KBLK + lane * 8);

            uint32_t aop[2][4];
#pragma unroll
            for (int h = 0; h < 2; h++) {
                float dd[4] = {0.f, 0.f, 0.f, 0.f};
#pragma unroll
                for (int ks = 0; ks < 8; ks++)
                    mma8(dd, qh4[h][ks].x, qh4[h][ks].y, qh4[h][ks].z, qh4[h][ks].w, kk[ks].x, kk[ks].y);
                float p0 = __expf(dd[0]) * invs[h][0], p1 = __expf(dd[1]) * invs[h][0];
                float p2 = __expf(dd[2]) * invs[h][1], p3 = __expf(dd[3]) * invs[h][1];
                int co = kt * TK + nt * 8 + 2 * tg;
                if (vr0[h]) *(float2*)(arow0[h] + co) = make_float2(p0, p1);
                if (vr8[h]) *(float2*)(arow8[h] + co) = make_float2(p2, p3);
                uint32_t h0 = rna(p0), h1 = rna(p1), h2 = rna(p2), h3 = rna(p3);
                uint32_t x00 = __shfl_sync(0xffffffffu, h0, src0), x01 = __shfl_sync(0xffffffffu, h1, src0);
                uint32_t x20 = __shfl_sync(0xffffffffu, h2, src0), x21 = __shfl_sync(0xffffffffu, h3, src0);
                uint32_t y00 = __shfl_sync(0xffffffffu, h0, src2), y01 = __shfl_sync(0xffffffffu, h1, src2);
                uint32_t y20 = __shfl_sync(0xffffffffu, h2, src2), y21 = __shfl_sync(0xffffffffu, h3, src2);
                aop[h][0] = odd ? x01 : x00; aop[h][1] = odd ? x21 : x20;
                aop[h][2] = odd ? y01 : y00; aop[h][3] = odd ? y21 : y20;
            }
#pragma unroll
            for (int ntd = 0; ntd < 8; ntd++) {
                uint2 vv = *(const uint2*)(sm + VOFF + ntd * VNTD + nt * KBLK + lane * 8);
#pragma unroll
                for (int h = 0; h < 2; h++)
                    mma8(avD[h][ntd], aop[h][0], aop[h][1], aop[h][2], aop[h][3], vv.x, vv.y);
            }
        }
    }

#pragma unroll
    for (int h = 0; h < 2; h++) {
        int rb0 = (2 * w + h) * 16 + g;
        float* orow0 = out + ((size_t)bh * L + rows_s[rb0]) * D;
        float* orow8 = out + ((size_t)bh * L + rows_s[rb0 + 8]) * D;
#pragma unroll
        for (int ntd = 0; ntd < 8; ntd++) {
            int dc = ntd * 8 + 2 * tg;
            if (vr0[h]) *(float2*)(orow0 + dc) = make_float2(avD[h][ntd][0], avD[h][ntd][1]);
            if (vr8[h]) *(float2*)(orow8 + dc) = make_float2(avD[h][ntd][2], avD[h][ntd][3]);
        }
    }
}

// ---------------------------------------------------------------------------
extern "C" void kernel_launch(void* const* d_in, const int* in_sizes, int n_in,
                              void* d_out, int out_size) {
    const float* q  = (const float*)d_in[0];
    const float* k  = (const float*)d_in[1];
    const float* v  = (const float*)d_in[2];
    const float* gw = (const float*)d_in[3];
    const float* gb = (const float*)d_in[4];

    const long long OUTE = (long long)BH * L * D;
    const long long ATTE = (long long)BH * L * L;
    float* outp = nullptr; float* attnp = nullptr;
    if ((long long)out_size == OUTE + ATTE) { outp = (float*)d_out; attnp = (float*)d_out + OUTE; }
    else if ((long long)out_size == ATTE)   { attnp = (float*)d_out; }
    else                                    { outp = (float*)d_out; }

    cudaFuncSetAttribute(attn_fat, cudaFuncAttributeMaxDynamicSharedMemorySize, SMEMB);
    gate_init<<<1, 64>>>();
    gate_kernel<<<BH * 8, 256>>>(q, gw, gb);
    attn_fat<<<dim3(48, BH), 128, SMEMB>>>(q, k, v, attnp, outp);
}

// round 13
// speedup vs baseline: 1.5331x; 1.1634x over previous
#include <cuda_runtime.h>
#include <cstdint>

#define BH 32
#define L 2048
#define D 64
#define TQ 128
#define TK 128
#define NTILE (L / TK)
#define WIN 2

#define KOFF 1024
#define KBLK 272                 // K/V (nt*8+ks) block stride: 256B data + 16B pad
#define QBLK 528                 // Q A-frag block stride: 512B data + 16B pad
#define VOFF (KOFF + 128 * KBLK) // 35840
#define VNTD 4368                // ntd stride: 16*272 + 16
#define SMEMB (VOFF + 8 * VNTD)  // 70784

__device__ __forceinline__ uint32_t rna(float x) {
    uint32_t r; asm("cvt.rna.tf32.f32 %0, %1;" : "=r"(r) : "f"(x)); return r;
}
__device__ __forceinline__ void mma8(float* d, uint32_t a0, uint32_t a1, uint32_t a2, uint32_t a3,
                                     uint32_t b0, uint32_t b1) {
    asm volatile("mma.sync.aligned.m16n8k8.row.col.f32.tf32.tf32.f32 "
        "{%0,%1,%2,%3}, {%4,%5,%6,%7}, {%8,%9}, {%0,%1,%2,%3};"
        : "+f"(d[0]), "+f"(d[1]), "+f"(d[2]), "+f"(d[3])
        : "r"(a0), "r"(a1), "r"(a2), "r"(a3), "r"(b0), "r"(b1));
}

__device__ int g_perm[BH][L];
__device__ int g_cnt[BH][2];
__device__ float g_out_scr[(size_t)BH * L * D];
__device__ float g_attn_scr[(size_t)BH * L * L];

// ---------------------------------------------------------------------------
__global__ void gate_init() {
    int t = threadIdx.x;
    if (t < BH) { g_cnt[t][0] = 0; g_cnt[t][1] = 0; }
}

__global__ void __launch_bounds__(256)
gate_kernel(const float* __restrict__ q, const float* __restrict__ gw, const float* __restrict__ gb) {
    __shared__ float4 w_s[16];
    const int bh = blockIdx.x >> 3, seg = blockIdx.x & 7;
    const int t = threadIdx.x;
    if (t < 16) w_s[t] = ((const float4*)gw)[t];
    __syncthreads();
    const int r = seg * 256 + t;
    const float4* qr = (const float4*)(q + ((size_t)bh * L + r) * D);
    float s = gb[0];
#pragma unroll
    for (int c = 0; c < 16; c++) {
        float4 a = qr[c], w = w_s[c];
        s += a.x * w.x + a.y * w.y + a.z * w.z + a.w * w.w;
    }
    if (s > 0.f) g_perm[bh][atomicAdd(&g_cnt[bh][0], 1)] = r;
    else         g_perm[bh][L - 1 - atomicAdd(&g_cnt[bh][1], 1)] = r;
}

// ---------------------------------------------------------------------------
// stage one K tile (128 keys x 64 dims) as tf32-hi B-fragments. 256 threads.
// ---------------------------------------------------------------------------
__device__ __forceinline__ void stage_k(const float* __restrict__ kg, char* sm, int t) {
#pragma unroll
    for (int it = 0; it < 4; it++) {
        int u = t + it * 256;
        int ks = u & 7, key = u >> 3;
        const float4* kr = (const float4*)(kg + (size_t)key * D);
        float4 a = kr[2 * ks], b = kr[2 * ks + 1];
        int nt = key >> 3, gg = key & 7;
        char* bp = sm + KOFF + (nt * 8 + ks) * KBLK + gg * 32;
        uint4 w0 = make_uint4(rna(a.x), rna(b.x), rna(a.y), rna(b.y));
        uint4 w1 = make_uint4(rna(a.z), rna(b.z), rna(a.w), rna(b.w));
        *(uint4*)bp = w0;
        *(uint4*)(bp + 16) = w1;
    }
}

// ---------------------------------------------------------------------------
// Fat kernel (256 threads, 8 warps): bx<16 -> gated (128 rows, 16 rows/warp,
// round-10 code verbatim); bx in [16,48) -> windowed (each warp up to 8 rows
// at stride 256).
// ---------------------------------------------------------------------------
__global__ void __launch_bounds__(256, 2)
attn_fat(const float* __restrict__ q, const float* __restrict__ k,
         const float* __restrict__ v, float* attnp, float* outp) {
    extern __shared__ __align__(16) char sm[];
    float* attn = attnp ? attnp : g_attn_scr;
    float* out  = outp  ? outp  : g_out_scr;
    const int bh = blockIdx.y, bx = blockIdx.x;
    const int t = threadIdx.x, w = t >> 5, lane = t & 31;
    const int g = lane >> 2, tg = lane & 3;

    // ================= windowed rows =================
    if (bx >= 16) {
        const int nw = L - g_cnt[bh][0];
#pragma unroll 1
        for (int rr = 0; rr < 8; rr++) {
            const int widx = (bx - 16) * 8 + w + rr * 256;
            if (widx >= nw) break;
            const int i = g_perm[bh][L - 1 - widx];
            const int j0 = max(0, i - WIN), j1 = min(L - 1, i + WIN);
            const int n = j1 - j0 + 1;
            const float* qr = q + ((size_t)bh * L + i) * D;
            float q0 = qr[lane], q1 = qr[lane + 32];
            float p[5], mx = -3.0e38f;
#pragma unroll
            for (int jj = 0; jj < 5; jj++) {
                float sc = -3.0e38f;
                if (jj < n) {
                    const float* kr = k + ((size_t)bh * L + j0 + jj) * D;
                    float d = q0 * kr[lane] + q1 * kr[lane + 32];
#pragma unroll
                    for (int o = 16; o > 0; o >>= 1) d += __shfl_xor_sync(0xffffffffu, d, o);
                    sc = d * 0.125f;
                }
                p[jj] = sc; mx = fmaxf(mx, sc);
            }
            float sum = 0.f;
#pragma unroll
            for (int jj = 0; jj < 5; jj++) { p[jj] = (jj < n) ? __expf(p[jj] - mx) : 0.f; sum += p[jj]; }
            float inv = 1.0f / sum;
#pragma unroll
            for (int jj = 0; jj < 5; jj++) p[jj] *= inv;

            float4* arow4 = (float4*)(attn + ((size_t)bh * L + i) * (size_t)L);
            const int s_lo = j0 >> 2, s_hi = j1 >> 2;
#pragma unroll
            for (int it = 0; it < 16; it++) {
                int s4 = lane + it * 32;
                if (s4 < s_lo || s4 > s_hi) arow4[s4] = make_float4(0.f, 0.f, 0.f, 0.f);
            }
            if (lane <= s_hi - s_lo) {
                int s4 = s_lo + lane;
                float vv[4];
#pragma unroll
                for (int e = 0; e < 4; e++) {
                    int idx = s4 * 4 + e;
                    vv[e] = (idx >= j0 && idx <= j1) ? p[idx - j0] : 0.f;
                }
                arow4[s4] = make_float4(vv[0], vv[1], vv[2], vv[3]);
            }
            float o0 = 0.f, o1 = 0.f;
#pragma unroll
            for (int jj = 0; jj < 5; jj++) {
                if (jj < n) {
                    const float* vr = v + ((size_t)bh * L + j0 + jj) * D;
                    o0 += p[jj] * vr[lane];
                    o1 += p[jj] * vr[lane + 32];
                }
            }
            float* orow = out + ((size_t)bh * L + i) * D;
            orow[lane] = o0; orow[lane + 32] = o1;
        }
        return;
    }

    // ================= gated rows (round-10 verbatim) =================
    const int ng = g_cnt[bh][0];
    const int base = bx * TQ;
    if (base >= ng) return;
    int* rows_s = (int*)sm;

    if (t < TQ) { int s = base + t; rows_s[t] = g_perm[bh][s < ng ? s : ng - 1]; }
    __syncthreads();

    // ---- stage Q A-frags (x 1/8, tf32) into K region with QBLK stride ----
#pragma unroll
    for (int it = 0; it < 2; it++) {
        int u = t + it * 256;
        int ks = u & 7, rp = (u >> 3) & 7, wt = u >> 6;
        int r0 = wt * 16 + rp, r1 = r0 + 8;
        const float4* q0 = (const float4*)(q + ((size_t)bh * L + rows_s[r0]) * D);
        const float4* q1 = (const float4*)(q + ((size_t)bh * L + rows_s[r1]) * D);
        float4 a0 = q0[2 * ks], a1 = q0[2 * ks + 1];
        float4 b0 = q1[2 * ks], b1 = q1[2 * ks + 1];
        char* bp = sm + KOFF + (wt * 8 + ks) * QBLK + rp * 64;
        *(uint4*)bp        = make_uint4(rna(a0.x * .125f), rna(b0.x * .125f), rna(a1.x * .125f), rna(b1.x * .125f));
        *(uint4*)(bp + 16) = make_uint4(rna(a0.y * .125f), rna(b0.y * .125f), rna(a1.y * .125f), rna(b1.y * .125f));
        *(uint4*)(bp + 32) = make_uint4(rna(a0.z * .125f), rna(b0.z * .125f), rna(a1.z * .125f), rna(b1.z * .125f));
        *(uint4*)(bp + 48) = make_uint4(rna(a0.w * .125f), rna(b0.w * .125f), rna(a1.w * .125f), rna(b1.w * .125f));
    }
    __syncthreads();

    uint4 qh4[8];
#pragma unroll
    for (int ks = 0; ks < 8; ks++)
        qh4[ks] = *(const uint4*)(sm + KOFF + (w * 8 + ks) * QBLK + lane * 16);
    __syncthreads();   // all qh4 loads done before pass A overwrites the region

    // ---------------- Pass A: row sums ----------------
    float sum0 = 0.f, sum8 = 0.f;
    for (int kt = 0; kt < NTILE; kt++) {
        __syncthreads();
        stage_k(k + ((size_t)bh * L + kt * TK) * D, sm, t);
        __syncthreads();
        for (int nt = 0; nt < 16; nt++) {
            float dd[4] = {0.f, 0.f, 0.f, 0.f};
#pragma unroll
            for (int ks = 0; ks < 8; ks++) {
                uint2 kk = *(const uint2*)(sm + KOFF + (nt * 8 + ks) * KBLK + lane * 8);
                mma8(dd, qh4[ks].x, qh4[ks].y, qh4[ks].z, qh4[ks].w, kk.x, kk.y);
            }
            sum0 += __expf(dd[0]) + __expf(dd[1]);
            sum8 += __expf(dd[2]) + __expf(dd[3]);
        }
    }
    sum0 += __shfl_xor_sync(0xffffffffu, sum0, 1);
    sum0 += __shfl_xor_sync(0xffffffffu, sum0, 2);
    sum8 += __shfl_xor_sync(0xffffffffu, sum8, 1);
    sum8 += __shfl_xor_sync(0xffffffffu, sum8, 2);
    const float inv0 = 1.f / sum0, inv8 = 1.f / sum8;

    // ---------------- Pass B: probs + AV ----------------
    const int rb0 = w * 16 + g;
    const bool vr0 = base + rb0 < ng, vr8 = base + rb0 + 8 < ng;
    float* arow0 = attn + ((size_t)bh * L + rows_s[rb0]) * (size_t)L;
    float* arow8 = attn + ((size_t)bh * L + rows_s[rb0 + 8]) * (size_t)L;
    float avD[8][4];
#pragma unroll
    for (int i = 0; i < 8; i++) { avD[i][0] = avD[i][1] = avD[i][2] = avD[i][3] = 0.f; }

    const int src0 = (lane & 28) | (tg >> 1);
    const int src2 = src0 + 2;
    const bool odd = tg & 1;

    for (int kt = 0; kt < NTILE; kt++) {
        __syncthreads();
        stage_k(k + ((size_t)bh * L + kt * TK) * D, sm, t);
        {   // stage V: unit = (key-pair, c4): 2 LDG.128 -> 4 STS.64
            const float* vg = v + ((size_t)bh * L + kt * TK) * D;
#pragma unroll
            for (int it = 0; it < 4; it++) {
                int u = t + it * 256;
                int c4 = u & 15, pr = u >> 4;
                int nt = pr >> 2, ttg = pr & 3;
                int key0 = nt * 8 + ttg;
                float4 v0 = ((const float4*)(vg + (size_t)key0 * D))[c4];
                float4 v1 = ((const float4*)(vg + (size_t)(key0 + 4) * D))[c4];
                int d0 = 4 * c4;
                int ntd = d0 >> 3, g0 = d0 & 7;
                char* bp = sm + VOFF + ntd * VNTD + nt * KBLK + ttg * 8;
                *(uint2*)(bp + (g0 + 0) * 32) = make_uint2(rna(v0.x), rna(v1.x));
                *(uint2*)(bp + (g0 + 1) * 32) = make_uint2(rna(v0.y), rna(v1.y));
                *(uint2*)(bp + (g0 + 2) * 32) = make_uint2(rna(v0.z), rna(v1.z));
                *(uint2*)(bp + (g0 + 3) * 32) = make_uint2(rna(v0.w), rna(v1.w));
            }
        }
        __syncthreads();

        for (int nt = 0; nt < 16; nt++) {
            float dd[4] = {0.f, 0.f, 0.f, 0.f};
#pragma unroll
            for (int ks = 0; ks < 8; ks++) {
                uint2 kk = *(const uint2*)(sm + KOFF + (nt * 8 + ks) * KBLK + lane * 8);
                mma8(dd, qh4[ks].x, qh4[ks].y, qh4[ks].z, qh4[ks].w, kk.x, kk.y);
            }
            float p0 = __expf(dd[0]) * inv0, p1 = __expf(dd[1]) * inv0;
            float p2 = __expf(dd[2]) * inv8, p3 = __expf(dd[3]) * inv8;
            int co = kt * TK + nt * 8 + 2 * tg;
            if (vr0) *(float2*)(arow0 + co) = make_float2(p0, p1);
            if (vr8) *(float2*)(arow8 + co) = make_float2(p2, p3);
            uint32_t h0 = rna(p0), h1 = rna(p1), h2 = rna(p2), h3 = rna(p3);
            uint32_t x00 = __shfl_sync(0xffffffffu, h0, src0), x01 = __shfl_sync(0xffffffffu, h1, src0);
            uint32_t x20 = __shfl_sync(0xffffffffu, h2, src0), x21 = __shfl_sync(0xffffffffu, h3, src0);
            uint32_t y00 = __shfl_sync(0xffffffffu, h0, src2), y01 = __shfl_sync(0xffffffffu, h1, src2);
            uint32_t y20 = __shfl_sync(0xffffffffu, h2, src2), y21 = __shfl_sync(0xffffffffu, h3, src2);
            uint32_t a0 = odd ? x01 : x00, a1 = odd ? x21 : x20;
            uint32_t a2 = odd ? y01 : y00, a3 = odd ? y21 : y20;
#pragma unroll
            for (int ntd = 0; ntd < 8; ntd++) {
                uint2 vv = *(const uint2*)(sm + VOFF + ntd * VNTD + nt * KBLK + lane * 8);
                mma8(avD[ntd], a0, a1, a2, a3, vv.x, vv.y);
            }
        }
    }

    float* orow0 = out + ((size_t)bh * L + rows_s[rb0]) * D;
    float* orow8 = out + ((size_t)bh * L + rows_s[rb0 + 8]) * D;
#pragma unroll
    for (int ntd = 0; ntd < 8; ntd++) {
        int dc = ntd * 8 + 2 * tg;
        if (vr0) *(float2*)(orow0 + dc) = make_float2(avD[ntd][0], avD[ntd][1]);
        if (vr8) *(float2*)(orow8 + dc) = make_float2(avD[ntd][2], avD[ntd][3]);
    }
}

// ---------------------------------------------------------------------------
extern "C" void kernel_launch(void* const* d_in, const int* in_sizes, int n_in,
                              void* d_out, int out_size) {
    const float* q  = (const float*)d_in[0];
    const float* k  = (const float*)d_in[1];
    const float* v  = (const float*)d_in[2];
    const float* gw = (const float*)d_in[3];
    const float* gb = (const float*)d_in[4];

    const long long OUTE = (long long)BH * L * D;
    const long long ATTE = (long long)BH * L * L;
    float* outp = nullptr; float* attnp = nullptr;
    if ((long long)out_size == OUTE + ATTE) { outp = (float*)d_out; attnp = (float*)d_out + OUTE; }
    else if ((long long)out_size == ATTE)   { attnp = (float*)d_out; }
    else                                    { outp = (float*)d_out; }

    cudaFuncSetAttribute(attn_fat, cudaFuncAttributeMaxDynamicSharedMemorySize, SMEMB);
    gate_init<<<1, 64>>>();
    gate_kernel<<<BH * 8, 256>>>(q, gw, gb);
    attn_fat<<<dim3(48, BH), 256, SMEMB>>>(q, k, v, attnp, outp);
}

// round 15
// speedup vs baseline: 2.3996x; 1.5653x over previous
#include <cuda_runtime.h>
#include <cstdint>

#define BH 32
#define L 2048
#define D 64
#define TQ 128
#define TK 128
#define NTILE (L / TK)
#define WIN 2

// bf16 fragment smem layout
#define QOFF 1024
#define QBLK 528                  // Q A-frag block: 512B + 16 pad
#define KOFF (QOFF + 32 * QBLK)   // 17920
#define FBLK 272                  // K/V frag block: 256B + 16 pad
#define VOFF (KOFF + 64 * FBLK)   // 35328
#define SMEMB (VOFF + 64 * FBLK)  // 52736

__device__ __forceinline__ uint32_t pkbf(float lo, float hi) {
    uint32_t r; asm("cvt.rn.bf16x2.f32 %0, %1, %2;" : "=r"(r) : "f"(hi), "f"(lo)); return r;
}
__device__ __forceinline__ void mma16(float* d, uint32_t a0, uint32_t a1, uint32_t a2, uint32_t a3,
                                      uint32_t b0, uint32_t b1) {
    asm volatile("mma.sync.aligned.m16n8k16.row.col.f32.bf16.bf16.f32 "
        "{%0,%1,%2,%3}, {%4,%5,%6,%7}, {%8,%9}, {%0,%1,%2,%3};"
        : "+f"(d[0]), "+f"(d[1]), "+f"(d[2]), "+f"(d[3])
        : "r"(a0), "r"(a1), "r"(a2), "r"(a3), "r"(b0), "r"(b1));
}

__device__ int g_perm[BH][L];
__device__ int g_cnt[BH][2];
__device__ float g_out_scr[(size_t)BH * L * D];
__device__ float g_attn_scr[(size_t)BH * L * L];

// ---------------------------------------------------------------------------
__global__ void gate_init() {
    int t = threadIdx.x;
    if (t < BH) { g_cnt[t][0] = 0; g_cnt[t][1] = 0; }
}

__global__ void __launch_bounds__(256)
gate_kernel(const float* __restrict__ q, const float* __restrict__ gw, const float* __restrict__ gb) {
    __shared__ float4 w_s[16];
    const int bh = blockIdx.x >> 3, seg = blockIdx.x & 7;
    const int t = threadIdx.x;
    if (t < 16) w_s[t] = ((const float4*)gw)[t];
    __syncthreads();
    const int r = seg * 256 + t;
    const float4* qr = (const float4*)(q + ((size_t)bh * L + r) * D);
    float s = gb[0];
#pragma unroll
    for (int c = 0; c < 16; c++) {
        float4 a = qr[c], w = w_s[c];
        s += a.x * w.x + a.y * w.y + a.z * w.z + a.w * w.w;
    }
    if (s > 0.f) g_perm[bh][atomicAdd(&g_cnt[bh][0], 1)] = r;
    else         g_perm[bh][L - 1 - atomicAdd(&g_cnt[bh][1], 1)] = r;
}

// ---------------------------------------------------------------------------
// stage one K tile (128 keys x 64 dims) as bf16 B-fragments for m16n8k16.
// block (nt*4+ksI): lane(g,tg) word = {K[key][16ksI+2tg..+1], K[key][16ksI+2tg+8..+9]}
// ---------------------------------------------------------------------------
__device__ __forceinline__ void stage_k(const float* __restrict__ kg, char* sm, int t) {
#pragma unroll
    for (int it = 0; it < 2; it++) {
        int u = t + it * 256;
        int key = u >> 2, ksI = u & 3;
        const float4* kr = (const float4*)(kg + (size_t)key * D + 16 * ksI);
        float4 f0 = kr[0], f1 = kr[1], f2 = kr[2], f3 = kr[3];
        const float d[16] = {f0.x, f0.y, f0.z, f0.w, f1.x, f1.y, f1.z, f1.w,
                             f2.x, f2.y, f2.z, f2.w, f3.x, f3.y, f3.z, f3.w};
        int nt = key >> 3, g = key & 7;
        char* bp = sm + KOFF + (nt * 4 + ksI) * FBLK + g * 32;
        *(uint4*)bp = make_uint4(pkbf(d[0], d[1]), pkbf(d[8], d[9]),
                                 pkbf(d[2], d[3]), pkbf(d[10], d[11]));
        *(uint4*)(bp + 16) = make_uint4(pkbf(d[4], d[5]), pkbf(d[12], d[13]),
                                        pkbf(d[6], d[7]), pkbf(d[14], d[15]));
    }
}

// ---------------------------------------------------------------------------
// gated rows: two-pass bf16 mma.sync attention. 256 threads, warp = 16 rows.
// ---------------------------------------------------------------------------
__global__ void __launch_bounds__(256, 2)
attn_gated(const float* __restrict__ q, const float* __restrict__ k,
           const float* __restrict__ v, float* attnp, float* outp) {
    extern __shared__ __align__(16) char sm[];
    float* attn = attnp ? attnp : g_attn_scr;
    float* out  = outp  ? outp  : g_out_scr;
    const int bh = blockIdx.y;
    const int ng = g_cnt[bh][0];
    const int base = (int)blockIdx.x * TQ;
    if (base >= ng) return;

    const int t = threadIdx.x, w = t >> 5, lane = t & 31;
    const int g = lane >> 2, tg = lane & 3;
    int* rows_s = (int*)sm;

    if (t < TQ) { int s = base + t; rows_s[t] = g_perm[bh][s < ng ? s : ng - 1]; }
    __syncthreads();

    // ---- stage Q A-frags (x 1/8, bf16): unit = (wt, rp, ksI), 1/thread ----
    {
        int wt = t >> 5, rp = (t >> 2) & 7, ksI = t & 3;
        int r0 = wt * 16 + rp, r1 = r0 + 8;
        const float4* q0p = (const float4*)(q + ((size_t)bh * L + rows_s[r0]) * D + 16 * ksI);
        const float4* q1p = (const float4*)(q + ((size_t)bh * L + rows_s[r1]) * D + 16 * ksI);
        float4 a4[4] = {q0p[0], q0p[1], q0p[2], q0p[3]};
        float4 b4[4] = {q1p[0], q1p[1], q1p[2], q1p[3]};
        float qa[16], qb[16];
#pragma unroll
        for (int i = 0; i < 4; i++) {
            qa[4 * i] = a4[i].x * .125f; qa[4 * i + 1] = a4[i].y * .125f;
            qa[4 * i + 2] = a4[i].z * .125f; qa[4 * i + 3] = a4[i].w * .125f;
            qb[4 * i] = b4[i].x * .125f; qb[4 * i + 1] = b4[i].y * .125f;
            qb[4 * i + 2] = b4[i].z * .125f; qb[4 * i + 3] = b4[i].w * .125f;
        }
        char* bp = sm + QOFF + (wt * 4 + ksI) * QBLK + rp * 64;
#pragma unroll
        for (int tgi = 0; tgi < 4; tgi++) {
            *(uint4*)(bp + tgi * 16) = make_uint4(
                pkbf(qa[2 * tgi], qa[2 * tgi + 1]), pkbf(qb[2 * tgi], qb[2 * tgi + 1]),
                pkbf(qa[2 * tgi + 8], qa[2 * tgi + 9]), pkbf(qb[2 * tgi + 8], qb[2 * tgi + 9]));
        }
    }
    __syncthreads();

    uint4 qA[4];
#pragma unroll
    for (int ksI = 0; ksI < 4; ksI++)
        qA[ksI] = *(const uint4*)(sm + QOFF + (w * 4 + ksI) * QBLK + lane * 16);

    // ---------------- Pass A: row sums ----------------
    float sum0 = 0.f, sum8 = 0.f;
    for (int kt = 0; kt < NTILE; kt++) {
        __syncthreads();
        stage_k(k + ((size_t)bh * L + kt * TK) * D, sm, t);
        __syncthreads();
        for (int nt = 0; nt < 16; nt++) {
            float dd[4] = {0.f, 0.f, 0.f, 0.f};
#pragma unroll
            for (int ks = 0; ks < 4; ks++) {
                uint2 kk = *(const uint2*)(sm + KOFF + (nt * 4 + ks) * FBLK + lane * 8);
                mma16(dd, qA[ks].x, qA[ks].y, qA[ks].z, qA[ks].w, kk.x, kk.y);
            }
            sum0 += __expf(dd[0]) + __expf(dd[1]);
            sum8 += __expf(dd[2]) + __expf(dd[3]);
        }
    }
    sum0 += __shfl_xor_sync(0xffffffffu, sum0, 1);
    sum0 += __shfl_xor_sync(0xffffffffu, sum0, 2);
    sum8 += __shfl_xor_sync(0xffffffffu, sum8, 1);
    sum8 += __shfl_xor_sync(0xffffffffu, sum8, 2);
    const float inv0 = 1.f / sum0, inv8 = 1.f / sum8;

    // ---------------- Pass B: probs + AV ----------------
    const int rb0 = w * 16 + g;
    const bool vr0 = base + rb0 < ng, vr8 = base + rb0 + 8 < ng;
    float* arow0 = attn + ((size_t)bh * L + rows_s[rb0]) * (size_t)L;
    float* arow8 = attn + ((size_t)bh * L + rows_s[rb0 + 8]) * (size_t)L;
    float avD[8][4];
#pragma unroll
    for (int i = 0; i < 8; i++) { avD[i][0] = avD[i][1] = avD[i][2] = avD[i][3] = 0.f; }

    for (int kt = 0; kt < NTILE; kt++) {
        __syncthreads();
        stage_k(k + ((size_t)bh * L + kt * TK) * D, sm, t);
        {   // stage V bf16 B-frags: unit = (ntP, jp, c4); 1024 units = 4 iters
            const float* vg = v + ((size_t)bh * L + kt * TK) * D;
#pragma unroll
            for (int it = 0; it < 4; it++) {
                int u = t + it * 256;
                int c4 = u & 15, pr = u >> 4;
                int ntP = pr >> 3, jp = pr & 7;
                int k0 = 16 * ntP + 2 * jp;
                float4 v0 = ((const float4*)(vg + (size_t)k0 * D))[c4];
                float4 v1 = ((const float4*)(vg + (size_t)(k0 + 1) * D))[c4];
                float f0[4] = {v0.x, v0.y, v0.z, v0.w};
                float f1[4] = {v1.x, v1.y, v1.z, v1.w};
                int ttg = jp & 3, half = jp >> 2;
#pragma unroll
                for (int e = 0; e < 4; e++) {
                    int d = 4 * c4 + e;
                    char* p = sm + VOFF + (ntP * 8 + (d >> 3)) * FBLK + (4 * (d & 7) + ttg) * 8 + half * 4;
                    *(uint32_t*)p = pkbf(f0[e], f1[e]);
                }
            }
        }
        __syncthreads();

        for (int ntP = 0; ntP < 8; ntP++) {
            int nt0 = 2 * ntP, nt1 = nt0 + 1;
            float d0[4] = {0.f, 0.f, 0.f, 0.f}, d1[4] = {0.f, 0.f, 0.f, 0.f};
#pragma unroll
            for (int ks = 0; ks < 4; ks++) {
                uint2 k0 = *(const uint2*)(sm + KOFF + (nt0 * 4 + ks) * FBLK + lane * 8);
                uint2 k1 = *(const uint2*)(sm + KOFF + (nt1 * 4 + ks) * FBLK + lane * 8);
                mma16(d0, qA[ks].x, qA[ks].y, qA[ks].z, qA[ks].w, k0.x, k0.y);
                mma16(d1, qA[ks].x, qA[ks].y, qA[ks].z, qA[ks].w, k1.x, k1.y);
            }
            float p00 = __expf(d0[0]) * inv0, p01 = __expf(d0[1]) * inv0;
            float p02 = __expf(d0[2]) * inv8, p03 = __expf(d0[3]) * inv8;
            float p10 = __expf(d1[0]) * inv0, p11 = __expf(d1[1]) * inv0;
            float p12 = __expf(d1[2]) * inv8, p13 = __expf(d1[3]) * inv8;
            int co0 = kt * TK + nt0 * 8 + 2 * tg;
            if (vr0) {
                *(float2*)(arow0 + co0) = make_float2(p00, p01);
                *(float2*)(arow0 + co0 + 8) = make_float2(p10, p11);
            }
            if (vr8) {
                *(float2*)(arow8 + co0) = make_float2(p02, p03);
                *(float2*)(arow8 + co0 + 8) = make_float2(p12, p13);
            }
            // P A-frag for AV: two D-frags packed, same thread, no shfl
            uint32_t a0 = pkbf(p00, p01), a1 = pkbf(p02, p03);
            uint32_t a2 = pkbf(p10, p11), a3 = pkbf(p12, p13);
#pragma unroll
            for (int ntd = 0; ntd < 8; ntd++) {
                uint2 vv = *(const uint2*)(sm + VOFF + (ntP * 8 + ntd) * FBLK + lane * 8);
                mma16(avD[ntd], a0, a1, a2, a3, vv.x, vv.y);
            }
        }
    }

    float* orow0 = out + ((size_t)bh * L + rows_s[rb0]) * D;
    float* orow8 = out + ((size_t)bh * L + rows_s[rb0 + 8]) * D;
#pragma unroll
    for (int ntd = 0; ntd < 8; ntd++) {
        int dc = ntd * 8 + 2 * tg;
        if (vr0) *(float2*)(orow0 + dc) = make_float2(avD[ntd][0], avD[ntd][1]);
        if (vr8) *(float2*)(orow8 + dc) = make_float2(avD[ntd][2], avD[ntd][3]);
    }
}

// ---------------------------------------------------------------------------
// windowed rows — one warp per row (round-10 verbatim, separate kernel)
// ---------------------------------------------------------------------------
__global__ void __launch_bounds__(256)
attn_win(const float* __restrict__ q, const float* __restrict__ k,
         const float* __restrict__ v, float* attnp, float* outp) {
    float* attn = attnp ? attnp : g_attn_scr;
    float* out  = outp  ? outp  : g_out_scr;
    const int bh = blockIdx.y;
    const int nw = L - g_cnt[bh][0];
    const int widx = blockIdx.x * 8 + (threadIdx.x >> 5);
    if (widx >= nw) return;
    const int lane = threadIdx.x & 31;
    const int i = g_perm[bh][L - 1 - widx];
    const int j0 = max(0, i - WIN), j1 = min(L - 1, i + WIN);
    const int n = j1 - j0 + 1;
    const float* qr = q + ((size_t)bh * L + i) * D;
    float q0 = qr[lane], q1 = qr[lane + 32];
    float p[5], mx = -3.0e38f;
#pragma unroll
    for (int jj = 0; jj < 5; jj++) {
        float sc = -3.0e38f;
        if (jj < n) {
            const float* kr = k + ((size_t)bh * L + j0 + jj) * D;
            float d = q0 * kr[lane] + q1 * kr[lane + 32];
#pragma unroll
            for (int o = 16; o > 0; o >>= 1) d += __shfl_xor_sync(0xffffffffu, d, o);
            sc = d * 0.125f;
        }
        p[jj] = sc; mx = fmaxf(mx, sc);
    }
    float sum = 0.f;
#pragma unroll
    for (int jj = 0; jj < 5; jj++) { p[jj] = (jj < n) ? __expf(p[jj] - mx) : 0.f; sum += p[jj]; }
    float inv = 1.0f / sum;
#pragma unroll
    for (int jj = 0; jj < 5; jj++) p[jj] *= inv;

    float4* arow4 = (float4*)(attn + ((size_t)bh * L + i) * (size_t)L);
    const int s_lo = j0 >> 2, s_hi = j1 >> 2;
#pragma unroll
    for (int it = 0; it < 16; it++) {
        int s4 = lane + it * 32;
        if (s4 < s_lo || s4 > s_hi) arow4[s4] = make_float4(0.f, 0.f, 0.f, 0.f);
    }
    if (lane <= s_hi - s_lo) {
        int s4 = s_lo + lane;
        float vv[4];
#pragma unroll
        for (int e = 0; e < 4; e++) {
            int idx = s4 * 4 + e;
            vv[e] = (idx >= j0 && idx <= j1) ? p[idx - j0] : 0.f;
        }
        arow4[s4] = make_float4(vv[0], vv[1], vv[2], vv[3]);
    }
    float o0 = 0.f, o1 = 0.f;
#pragma unroll
    for (int jj = 0; jj < 5; jj++) {
        if (jj < n) {
            const float* vr = v + ((size_t)bh * L + j0 + jj) * D;
            o0 += p[jj] * vr[lane];
            o1 += p[jj] * vr[lane + 32];
        }
    }
    float* orow = out + ((size_t)bh * L + i) * D;
    orow[lane] = o0; orow[lane + 32] = o1;
}

// ---------------------------------------------------------------------------
extern "C" void kernel_launch(void* const* d_in, const int* in_sizes, int n_in,
                              void* d_out, int out_size) {
    const float* q  = (const float*)d_in[0];
    const float* k  = (const float*)d_in[1];
    const float* v  = (const float*)d_in[2];
    const float* gw = (const float*)d_in[3];
    const float* gb = (const float*)d_in[4];

    const long long OUTE = (long long)BH * L * D;
    const long long ATTE = (long long)BH * L * L;
    float* outp = nullptr; float* attnp = nullptr;
    if ((long long)out_size == OUTE + ATTE) { outp = (float*)d_out; attnp = (float*)d_out + OUTE; }
    else if ((long long)out_size == ATTE)   { attnp = (float*)d_out; }
    else                                    { outp = (float*)d_out; }

    cudaFuncSetAttribute(attn_gated, cudaFuncAttributeMaxDynamicSharedMemorySize, SMEMB);
    gate_init<<<1, 64>>>();
    gate_kernel<<<BH * 8, 256>>>(q, gw, gb);
    attn_gated<<<dim3(L / TQ, BH), 256, SMEMB>>>(q, k, v, attnp, outp);
    attn_win<<<dim3(L / 8, BH), 256>>>(q, k, v, attnp, outp);
}

// round 16
// speedup vs baseline: 2.4555x; 1.0233x over previous
#include <cuda_runtime.h>
#include <cstdint>

#define BH 32
#define L 2048
#define D 64
#define TQ 128
#define TK 128
#define NTILE (L / TK)
#define WIN 2

// bf16 fragment smem layout
#define QOFF 1024
#define QBLK 528                  // Q A-frag block: 512B + 16 pad
#define KOFF (QOFF + 32 * QBLK)   // 17920
#define FBLK 272                  // K/V frag block: 256B + 16 pad
#define VOFF (KOFF + 64 * FBLK)   // 35328
#define SMEMB (VOFF + 64 * FBLK)  // 52736

__device__ __forceinline__ uint32_t pkbf(float lo, float hi) {
    uint32_t r; asm("cvt.rn.bf16x2.f32 %0, %1, %2;" : "=r"(r) : "f"(hi), "f"(lo)); return r;
}
__device__ __forceinline__ void mma16(float* d, uint32_t a0, uint32_t a1, uint32_t a2, uint32_t a3,
                                      uint32_t b0, uint32_t b1) {
    asm volatile("mma.sync.aligned.m16n8k16.row.col.f32.bf16.bf16.f32 "
        "{%0,%1,%2,%3}, {%4,%5,%6,%7}, {%8,%9}, {%0,%1,%2,%3};"
        : "+f"(d[0]), "+f"(d[1]), "+f"(d[2]), "+f"(d[3])
        : "r"(a0), "r"(a1), "r"(a2), "r"(a3), "r"(b0), "r"(b1));
}

__device__ int g_perm[BH][L];
__device__ int g_cnt[BH][2];
__device__ float g_out_scr[(size_t)BH * L * D];
__device__ float g_attn_scr[(size_t)BH * L * L];

// ---------------------------------------------------------------------------
__global__ void gate_init() {
    int t = threadIdx.x;
    if (t < BH) { g_cnt[t][0] = 0; g_cnt[t][1] = 0; }
}

__global__ void __launch_bounds__(256)
gate_kernel(const float* __restrict__ q, const float* __restrict__ gw, const float* __restrict__ gb) {
    __shared__ float4 w_s[16];
    const int bh = blockIdx.x >> 3, seg = blockIdx.x & 7;
    const int t = threadIdx.x;
    if (t < 16) w_s[t] = ((const float4*)gw)[t];
    __syncthreads();
    const int r = seg * 256 + t;
    const float4* qr = (const float4*)(q + ((size_t)bh * L + r) * D);
    float s = gb[0];
#pragma unroll
    for (int c = 0; c < 16; c++) {
        float4 a = qr[c], w = w_s[c];
        s += a.x * w.x + a.y * w.y + a.z * w.z + a.w * w.w;
    }
    if (s > 0.f) g_perm[bh][atomicAdd(&g_cnt[bh][0], 1)] = r;
    else         g_perm[bh][L - 1 - atomicAdd(&g_cnt[bh][1], 1)] = r;
}

// ---------------------------------------------------------------------------
// stage one K tile (128 keys x 64 dims) as bf16 B-fragments for m16n8k16.
// ---------------------------------------------------------------------------
__device__ __forceinline__ void stage_k(const float* __restrict__ kg, char* sm, int t) {
#pragma unroll
    for (int it = 0; it < 2; it++) {
        int u = t + it * 256;
        int key = u >> 2, ksI = u & 3;
        const float4* kr = (const float4*)(kg + (size_t)key * D + 16 * ksI);
        float4 f0 = kr[0], f1 = kr[1], f2 = kr[2], f3 = kr[3];
        const float d[16] = {f0.x, f0.y, f0.z, f0.w, f1.x, f1.y, f1.z, f1.w,
                             f2.x, f2.y, f2.z, f2.w, f3.x, f3.y, f3.z, f3.w};
        int nt = key >> 3, g = key & 7;
        char* bp = sm + KOFF + (nt * 4 + ksI) * FBLK + g * 32;
        *(uint4*)bp = make_uint4(pkbf(d[0], d[1]), pkbf(d[8], d[9]),
                                 pkbf(d[2], d[3]), pkbf(d[10], d[11]));
        *(uint4*)(bp + 16) = make_uint4(pkbf(d[4], d[5]), pkbf(d[12], d[13]),
                                        pkbf(d[6], d[7]), pkbf(d[14], d[15]));
    }
}

// ---------------------------------------------------------------------------
// gated rows: two-pass bf16 mma.sync attention. 256 threads, warp = 16 rows.
// ---------------------------------------------------------------------------
__global__ void __launch_bounds__(256, 2)
attn_gated(const float* __restrict__ q, const float* __restrict__ k,
           const float* __restrict__ v, float* attnp, float* outp) {
    extern __shared__ __align__(16) char sm[];
    float* attn = attnp ? attnp : g_attn_scr;
    float* out  = outp  ? outp  : g_out_scr;
    const int bh = blockIdx.y;
    const int ng = g_cnt[bh][0];
    const int base = (int)blockIdx.x * TQ;
    if (base >= ng) return;

    const int t = threadIdx.x, w = t >> 5, lane = t & 31;
    const int g = lane >> 2, tg = lane & 3;
    int* rows_s = (int*)sm;

    if (t < TQ) { int s = base + t; rows_s[t] = g_perm[bh][s < ng ? s : ng - 1]; }
    __syncthreads();

    // ---- stage Q A-frags (x 1/8, bf16): unit = (wt, rp, ksI), 1/thread ----
    {
        int wt = t >> 5, rp = (t >> 2) & 7, ksI = t & 3;
        int r0 = wt * 16 + rp, r1 = r0 + 8;
        const float4* q0p = (const float4*)(q + ((size_t)bh * L + rows_s[r0]) * D + 16 * ksI);
        const float4* q1p = (const float4*)(q + ((size_t)bh * L + rows_s[r1]) * D + 16 * ksI);
        float4 a4[4] = {q0p[0], q0p[1], q0p[2], q0p[3]};
        float4 b4[4] = {q1p[0], q1p[1], q1p[2], q1p[3]};
        float qa[16], qb[16];
#pragma unroll
        for (int i = 0; i < 4; i++) {
            qa[4 * i] = a4[i].x * .125f; qa[4 * i + 1] = a4[i].y * .125f;
            qa[4 * i + 2] = a4[i].z * .125f; qa[4 * i + 3] = a4[i].w * .125f;
            qb[4 * i] = b4[i].x * .125f; qb[4 * i + 1] = b4[i].y * .125f;
            qb[4 * i + 2] = b4[i].z * .125f; qb[4 * i + 3] = b4[i].w * .125f;
        }
        char* bp = sm + QOFF + (wt * 4 + ksI) * QBLK + rp * 64;
#pragma unroll
        for (int tgi = 0; tgi < 4; tgi++) {
            *(uint4*)(bp + tgi * 16) = make_uint4(
                pkbf(qa[2 * tgi], qa[2 * tgi + 1]), pkbf(qb[2 * tgi], qb[2 * tgi + 1]),
                pkbf(qa[2 * tgi + 8], qa[2 * tgi + 9]), pkbf(qb[2 * tgi + 8], qb[2 * tgi + 9]));
        }
    }
    __syncthreads();

    uint4 qA[4];
#pragma unroll
    for (int ksI = 0; ksI < 4; ksI++)
        qA[ksI] = *(const uint4*)(sm + QOFF + (w * 4 + ksI) * QBLK + lane * 16);

    // ---------------- Pass A: row sums ----------------
    float sum0 = 0.f, sum8 = 0.f;
    for (int kt = 0; kt < NTILE; kt++) {
        __syncthreads();
        stage_k(k + ((size_t)bh * L + kt * TK) * D, sm, t);
        __syncthreads();
        for (int nt = 0; nt < 16; nt++) {
            float dd[4] = {0.f, 0.f, 0.f, 0.f};
#pragma unroll
            for (int ks = 0; ks < 4; ks++) {
                uint2 kk = *(const uint2*)(sm + KOFF + (nt * 4 + ks) * FBLK + lane * 8);
                mma16(dd, qA[ks].x, qA[ks].y, qA[ks].z, qA[ks].w, kk.x, kk.y);
            }
            sum0 += __expf(dd[0]) + __expf(dd[1]);
            sum8 += __expf(dd[2]) + __expf(dd[3]);
        }
    }
    sum0 += __shfl_xor_sync(0xffffffffu, sum0, 1);
    sum0 += __shfl_xor_sync(0xffffffffu, sum0, 2);
    sum8 += __shfl_xor_sync(0xffffffffu, sum8, 1);
    sum8 += __shfl_xor_sync(0xffffffffu, sum8, 2);
    const float inv0 = 1.f / sum0, inv8 = 1.f / sum8;

    // ---------------- Pass B: probs + AV ----------------
    const int rb0 = w * 16 + g;
    const bool vr0 = base + rb0 < ng, vr8 = base + rb0 + 8 < ng;
    float* arow0 = attn + ((size_t)bh * L + rows_s[rb0]) * (size_t)L;
    float* arow8 = attn + ((size_t)bh * L + rows_s[rb0 + 8]) * (size_t)L;
    float avD[8][4];
#pragma unroll
    for (int i = 0; i < 8; i++) { avD[i][0] = avD[i][1] = avD[i][2] = avD[i][3] = 0.f; }

    for (int kt = 0; kt < NTILE; kt++) {
        __syncthreads();
        stage_k(k + ((size_t)bh * L + kt * TK) * D, sm, t);
        {   // stage V bf16 B-frags: unit = (ntP, jp, c4); 1024 units = 4 iters
            const float* vg = v + ((size_t)bh * L + kt * TK) * D;
#pragma unroll
            for (int it = 0; it < 4; it++) {
                int u = t + it * 256;
                int c4 = u & 15, pr = u >> 4;
                int ntP = pr >> 3, jp = pr & 7;
                int k0 = 16 * ntP + 2 * jp;
                float4 v0 = ((const float4*)(vg + (size_t)k0 * D))[c4];
                float4 v1 = ((const float4*)(vg + (size_t)(k0 + 1) * D))[c4];
                float f0[4] = {v0.x, v0.y, v0.z, v0.w};
                float f1[4] = {v1.x, v1.y, v1.z, v1.w};
                int ttg = jp & 3, half = jp >> 2;
#pragma unroll
                for (int e = 0; e < 4; e++) {
                    int d = 4 * c4 + e;
                    char* p = sm + VOFF + (ntP * 8 + (d >> 3)) * FBLK + (4 * (d & 7) + ttg) * 8 + half * 4;
                    *(uint32_t*)p = pkbf(f0[e], f1[e]);
                }
            }
        }
        __syncthreads();

        for (int ntP = 0; ntP < 8; ntP++) {
            int nt0 = 2 * ntP, nt1 = nt0 + 1;
            float d0[4] = {0.f, 0.f, 0.f, 0.f}, d1[4] = {0.f, 0.f, 0.f, 0.f};
#pragma unroll
            for (int ks = 0; ks < 4; ks++) {
                uint2 k0 = *(const uint2*)(sm + KOFF + (nt0 * 4 + ks) * FBLK + lane * 8);
                uint2 k1 = *(const uint2*)(sm + KOFF + (nt1 * 4 + ks) * FBLK + lane * 8);
                mma16(d0, qA[ks].x, qA[ks].y, qA[ks].z, qA[ks].w, k0.x, k0.y);
                mma16(d1, qA[ks].x, qA[ks].y, qA[ks].z, qA[ks].w, k1.x, k1.y);
            }
            float p00 = __expf(d0[0]) * inv0, p01 = __expf(d0[1]) * inv0;
            float p02 = __expf(d0[2]) * inv8, p03 = __expf(d0[3]) * inv8;
            float p10 = __expf(d1[0]) * inv0, p11 = __expf(d1[1]) * inv0;
            float p12 = __expf(d1[2]) * inv8, p13 = __expf(d1[3]) * inv8;
            int co0 = kt * TK + nt0 * 8 + 2 * tg;
            if (vr0) {
                *(float2*)(arow0 + co0) = make_float2(p00, p01);
                *(float2*)(arow0 + co0 + 8) = make_float2(p10, p11);
            }
            if (vr8) {
                *(float2*)(arow8 + co0) = make_float2(p02, p03);
                *(float2*)(arow8 + co0 + 8) = make_float2(p12, p13);
            }
            uint32_t a0 = pkbf(p00, p01), a1 = pkbf(p02, p03);
            uint32_t a2 = pkbf(p10, p11), a3 = pkbf(p12, p13);
#pragma unroll
            for (int ntd = 0; ntd < 8; ntd++) {
                uint2 vv = *(const uint2*)(sm + VOFF + (ntP * 8 + ntd) * FBLK + lane * 8);
                mma16(avD[ntd], a0, a1, a2, a3, vv.x, vv.y);
            }
        }
    }

    float* orow0 = out + ((size_t)bh * L + rows_s[rb0]) * D;
    float* orow8 = out + ((size_t)bh * L + rows_s[rb0 + 8]) * D;
#pragma unroll
    for (int ntd = 0; ntd < 8; ntd++) {
        int dc = ntd * 8 + 2 * tg;
        if (vr0) *(float2*)(orow0 + dc) = make_float2(avD[ntd][0], avD[ntd][1]);
        if (vr8) *(float2*)(orow8 + dc) = make_float2(avD[ntd][2], avD[ntd][3]);
    }
}

// ---------------------------------------------------------------------------
// windowed rows — one warp per row
// ---------------------------------------------------------------------------
__global__ void __launch_bounds__(256)
attn_win(const float* __restrict__ q, const float* __restrict__ k,
         const float* __restrict__ v, float* attnp, float* outp) {
    float* attn = attnp ? attnp : g_attn_scr;
    float* out  = outp  ? outp  : g_out_scr;
    const int bh = blockIdx.y;
    const int nw = L - g_cnt[bh][0];
    const int widx = blockIdx.x * 8 + (threadIdx.x >> 5);
    if (widx >= nw) return;
    const int lane = threadIdx.x & 31;
    const int i = g_perm[bh][L - 1 - widx];
    const int j0 = max(0, i - WIN), j1 = min(L - 1, i + WIN);
    const int n = j1 - j0 + 1;
    const float* qr = q + ((size_t)bh * L + i) * D;
    float q0 = qr[lane], q1 = qr[lane + 32];
    float p[5], mx = -3.0e38f;
#pragma unroll
    for (int jj = 0; jj < 5; jj++) {
        float sc = -3.0e38f;
        if (jj < n) {
            const float* kr = k + ((size_t)bh * L + j0 + jj) * D;
            float d = q0 * kr[lane] + q1 * kr[lane + 32];
#pragma unroll
            for (int o = 16; o > 0; o >>= 1) d += __shfl_xor_sync(0xffffffffu, d, o);
            sc = d * 0.125f;
        }
        p[jj] = sc; mx = fmaxf(mx, sc);
    }
    float sum = 0.f;
#pragma unroll
    for (int jj = 0; jj < 5; jj++) { p[jj] = (jj < n) ? __expf(p[jj] - mx) : 0.f; sum += p[jj]; }
    float inv = 1.0f / sum;
#pragma unroll
    for (int jj = 0; jj < 5; jj++) p[jj] *= inv;

    float4* arow4 = (float4*)(attn + ((size_t)bh * L + i) * (size_t)L);
    const int s_lo = j0 >> 2, s_hi = j1 >> 2;
#pragma unroll
    for (int it = 0; it < 16; it++) {
        int s4 = lane + it * 32;
        if (s4 < s_lo || s4 > s_hi) arow4[s4] = make_float4(0.f, 0.f, 0.f, 0.f);
    }
    if (lane <= s_hi - s_lo) {
        int s4 = s_lo + lane;
        float vv[4];
#pragma unroll
        for (int e = 0; e < 4; e++) {
            int idx = s4 * 4 + e;
            vv[e] = (idx >= j0 && idx <= j1) ? p[idx - j0] : 0.f;
        }
        arow4[s4] = make_float4(vv[0], vv[1], vv[2], vv[3]);
    }
    float o0 = 0.f, o1 = 0.f;
#pragma unroll
    for (int jj = 0; jj < 5; jj++) {
        if (jj < n) {
            const float* vr = v + ((size_t)bh * L + j0 + jj) * D;
            o0 += p[jj] * vr[lane];
            o1 += p[jj] * vr[lane + 32];
        }
    }
    float* orow = out + ((size_t)bh * L + i) * D;
    orow[lane] = o0; orow[lane + 32] = o1;
}

// ---------------------------------------------------------------------------
extern "C" void kernel_launch(void* const* d_in, const int* in_sizes, int n_in,
                              void* d_out, int out_size) {
    const float* q  = (const float*)d_in[0];
    const float* k  = (const float*)d_in[1];
    const float* v  = (const float*)d_in[2];
    const float* gw = (const float*)d_in[3];
    const float* gb = (const float*)d_in[4];

    const long long OUTE = (long long)BH * L * D;
    const long long ATTE = (long long)BH * L * L;
    float* outp = nullptr; float* attnp = nullptr;
    if ((long long)out_size == OUTE + ATTE) { outp = (float*)d_out; attnp = (float*)d_out + OUTE; }
    else if ((long long)out_size == ATTE)   { attnp = (float*)d_out; }
    else                                    { outp = (float*)d_out; }

    // one-time host-side infra (created on the uncaptured correctness call)
    static cudaStream_t s2 = nullptr;
    static cudaEvent_t evF = nullptr, evJ = nullptr;
    if (!s2) {
        cudaStreamCreateWithFlags(&s2, cudaStreamNonBlocking);
        cudaEventCreateWithFlags(&evF, cudaEventDisableTiming);
        cudaEventCreateWithFlags(&evJ, cudaEventDisableTiming);
    }

    cudaFuncSetAttribute(attn_gated, cudaFuncAttributeMaxDynamicSharedMemorySize, SMEMB);
    gate_init<<<1, 64>>>();
    gate_kernel<<<BH * 8, 256>>>(q, gw, gb);

    // fork: windowed rows run concurrently with gated rows
    cudaEventRecord(evF, 0);
    cudaStreamWaitEvent(s2, evF, 0);
    attn_win<<<dim3(L / 8, BH), 256, 0, s2>>>(q, k, v, attnp, outp);
    cudaEventRecord(evJ, s2);

    attn_gated<<<dim3(L / TQ, BH), 256, SMEMB>>>(q, k, v, attnp, outp);

    // join
    cudaStreamWaitEvent(0, evJ, 0);
}